// round 1
// baseline (speedup 1.0000x reference)
#include <cuda_runtime.h>
#include <math.h>

#define B_ 256
#define P_ 512
#define C_ 512
#define T_ 56
#define EPSV 1e-8f

// ---------------- static device scratch (allocation-free rule) ----------------
__device__ float g_xT[(size_t)T_ * B_ * C_];   // [t][b][c]   29.4 MB
__device__ float g_pT[(size_t)T_ * P_ * C_];   // [t][p][c]   58.7 MB
__device__ float g_xn[T_ * B_];                // [t][b]
__device__ float g_pn[T_ * P_];                // [t][p]
__device__ float g_sim[(size_t)T_ * B_ * P_];  // [t][b][p]   29.4 MB
__device__ float g_d2[(size_t)T_ * B_ * P_];   // [t][b][p]   29.4 MB

// ---------------- transpose: src [R][C][T] -> dst [T][R][C] ----------------
// which==0 : x  (R=B_),  which==1 : proto (R=P_)
__global__ void transpose_kernel(const float* __restrict__ src, int which) {
    __shared__ float tile[32][57];
    float* dst = which ? g_pT : g_xT;
    const int R = which ? P_ : B_;
    const int r  = blockIdx.x;        // b or p
    const int c0 = blockIdx.y * 32;   // channel chunk

    const float* s = src + (size_t)r * C_ * T_ + (size_t)c0 * T_;
    for (int idx = threadIdx.x; idx < 32 * T_; idx += blockDim.x)
        tile[idx / T_][idx % T_] = s[idx];          // contiguous read
    __syncthreads();
    for (int idx = threadIdx.x; idx < 32 * T_; idx += blockDim.x) {
        int t = idx >> 5, c = idx & 31;
        dst[(size_t)t * R * C_ + (size_t)r * C_ + c0 + c] = tile[c][t];  // coalesced write
    }
}

// ---------------- per-(t,row) L2 norm over C (one warp per output) ----------------
// which==0 : xn from g_xT (R=B_),  which==1 : pn from g_pT (R=P_)
__global__ void norm_kernel(int which) {
    const float* src = which ? g_pT : g_xT;
    float* dst = which ? g_pn : g_xn;
    const int R = which ? P_ : B_;
    int gw   = (blockIdx.x * blockDim.x + threadIdx.x) >> 5;  // t*R + r
    int lane = threadIdx.x & 31;
    if (gw >= T_ * R) return;
    const float* s = src + (size_t)gw * C_;
    float acc = 0.f;
    #pragma unroll 4
    for (int c = lane; c < C_; c += 32) { float v = s[c]; acc += v * v; }
    #pragma unroll
    for (int o = 16; o > 0; o >>= 1) acc += __shfl_xor_sync(0xffffffffu, acc, o);
    if (lane == 0) dst[gw] = sqrtf(acc);
}

// ---------------- fused dual-accumulator GEMM per t ----------------
// For each t: sim[b,p] = (x_t . proto_t) / max(xn*pn, eps)
//             d2[b,p]  = (fc_w*x_t) . proto_t
// Tile: 128 (b) x 64 (p), K-chunk 32, 256 threads, 8x4 micro-tile, two accumulators.
#define BT 128
#define PT 64
#define KT 32

__global__ __launch_bounds__(256, 2) void gemm_kernel(const float* __restrict__ fcw) {
    __shared__ float xs [KT][BT + 4];
    __shared__ float xws[KT][BT + 4];
    __shared__ float ps [KT][PT + 4];
    __shared__ float s_fcw[C_];

    const int t  = blockIdx.z;
    const int b0 = blockIdx.y * BT;
    const int p0 = blockIdx.x * PT;
    const int tid = threadIdx.x;
    const int tx = tid & 15;   // p dimension (4 cols each)
    const int ty = tid >> 4;   // b dimension (8 rows each)

    for (int i = tid; i < C_; i += 256) s_fcw[i] = fcw[i];

    float acc1[8][4], acc2[8][4];
    #pragma unroll
    for (int i = 0; i < 8; i++)
        #pragma unroll
        for (int j = 0; j < 4; j++) { acc1[i][j] = 0.f; acc2[i][j] = 0.f; }

    const float* xbase = g_xT + (size_t)t * B_ * C_ + (size_t)b0 * C_;
    const float* pbase = g_pT + (size_t)t * P_ * C_ + (size_t)p0 * C_;

    __syncthreads();  // s_fcw ready

    for (int kc = 0; kc < C_; kc += KT) {
        // stage X tile (128 x 32) + fc_w-scaled copy : 4 float4 per thread
        #pragma unroll
        for (int i = 0; i < 4; i++) {
            int idx = tid + i * 256;
            int r = idx >> 3, q = idx & 7;
            float4 v = *(const float4*)(xbase + (size_t)r * C_ + kc + q * 4);
            int k = q * 4;
            xs[k + 0][r] = v.x;  xs[k + 1][r] = v.y;
            xs[k + 2][r] = v.z;  xs[k + 3][r] = v.w;
            xws[k + 0][r] = v.x * s_fcw[kc + k + 0];
            xws[k + 1][r] = v.y * s_fcw[kc + k + 1];
            xws[k + 2][r] = v.z * s_fcw[kc + k + 2];
            xws[k + 3][r] = v.w * s_fcw[kc + k + 3];
        }
        // stage P tile (64 x 32) : 2 float4 per thread
        #pragma unroll
        for (int i = 0; i < 2; i++) {
            int idx = tid + i * 256;
            int r = idx >> 3, q = idx & 7;
            float4 v = *(const float4*)(pbase + (size_t)r * C_ + kc + q * 4);
            int k = q * 4;
            ps[k + 0][r] = v.x;  ps[k + 1][r] = v.y;
            ps[k + 2][r] = v.z;  ps[k + 3][r] = v.w;
        }
        __syncthreads();

        #pragma unroll
        for (int k = 0; k < KT; k++) {
            float4 bv = *(const float4*)&ps[k][tx * 4];
            float bb[4] = {bv.x, bv.y, bv.z, bv.w};
            float4 a0 = *(const float4*)&xs [k][ty * 8];
            float4 a1 = *(const float4*)&xs [k][ty * 8 + 4];
            float4 w0 = *(const float4*)&xws[k][ty * 8];
            float4 w1 = *(const float4*)&xws[k][ty * 8 + 4];
            float a[8]  = {a0.x, a0.y, a0.z, a0.w, a1.x, a1.y, a1.z, a1.w};
            float aw[8] = {w0.x, w0.y, w0.z, w0.w, w1.x, w1.y, w1.z, w1.w};
            #pragma unroll
            for (int i = 0; i < 8; i++)
                #pragma unroll
                for (int j = 0; j < 4; j++) {
                    acc1[i][j] = fmaf(a[i],  bb[j], acc1[i][j]);
                    acc2[i][j] = fmaf(aw[i], bb[j], acc2[i][j]);
                }
        }
        __syncthreads();
    }

    // epilogue: normalize dots -> sim, write sim + d2 (layout [t][b][p])
    float pnv[4];
    #pragma unroll
    for (int j = 0; j < 4; j++) pnv[j] = g_pn[t * P_ + p0 + tx * 4 + j];

    #pragma unroll
    for (int i = 0; i < 8; i++) {
        int r = b0 + ty * 8 + i;
        float xnv = g_xn[t * B_ + r];
        size_t off = (size_t)t * B_ * P_ + (size_t)r * P_ + p0 + tx * 4;
        float4 sv, dv;
        sv.x = acc1[i][0] / fmaxf(xnv * pnv[0], EPSV);
        sv.y = acc1[i][1] / fmaxf(xnv * pnv[1], EPSV);
        sv.z = acc1[i][2] / fmaxf(xnv * pnv[2], EPSV);
        sv.w = acc1[i][3] / fmaxf(xnv * pnv[3], EPSV);
        dv.x = acc2[i][0]; dv.y = acc2[i][1]; dv.z = acc2[i][2]; dv.w = acc2[i][3];
        *(float4*)(g_sim + off) = sv;
        *(float4*)(g_d2  + off) = dv;
    }
}

// ---------------- online softmax over t + folded FC + relu ----------------
__global__ void softmax_out_kernel(const float* __restrict__ fcb, float* __restrict__ out) {
    const int b = blockIdx.x;
    const int p = threadIdx.x;   // 512 threads
    const float* sp = g_sim + (size_t)b * P_ + p;
    const float* dp = g_d2  + (size_t)b * P_ + p;
    float m = -INFINITY, l = 0.f, acc = 0.f;
    #pragma unroll 4
    for (int t = 0; t < T_; t++) {
        float s = sp[(size_t)t * B_ * P_];
        float v = dp[(size_t)t * B_ * P_];
        float nm = fmaxf(m, s);
        float scale = __expf(m - nm);    // first iter: exp(-inf)=0
        l = l * scale; acc = acc * scale;
        float e = __expf(s - nm);
        l += e; acc += e * v;
        m = nm;
    }
    out[b * P_ + p] = fmaxf(acc / l + fcb[0], 0.f);
}

// ---------------- launch ----------------
extern "C" void kernel_launch(void* const* d_in, const int* in_sizes, int n_in,
                              void* d_out, int out_size) {
    const float* x     = (const float*)d_in[0];  // (B, C, H, W) == (B, C, T)
    const float* proto = (const float*)d_in[1];  // (P, C, T)
    const float* fcw   = (const float*)d_in[2];  // (1, C)
    const float* fcb   = (const float*)d_in[3];  // (1,)
    float* out = (float*)d_out;                  // (B, P)
    (void)in_sizes; (void)n_in; (void)out_size;

    transpose_kernel<<<dim3(B_, C_ / 32), 256>>>(x, 0);
    transpose_kernel<<<dim3(P_, C_ / 32), 256>>>(proto, 1);
    norm_kernel<<<(T_ * B_ * 32 + 255) / 256, 256>>>(0);
    norm_kernel<<<(T_ * P_ * 32 + 255) / 256, 256>>>(1);
    gemm_kernel<<<dim3(P_ / PT, B_ / BT, T_), 256>>>(fcw);
    softmax_out_kernel<<<B_, P_>>>(fcb, out);
}

// round 3
// speedup vs baseline: 1.0861x; 1.0861x over previous
#include <cuda_runtime.h>
#include <math.h>

#define B_ 256
#define P_ 512
#define C_ 512
#define T_ 56
#define EPSV 1e-8f

// ---------------- static device scratch (allocation-free rule) ----------------
__device__ float g_xT[(size_t)T_ * B_ * C_];   // [t][b][c]   29.4 MB
__device__ float g_pT[(size_t)T_ * P_ * C_];   // [t][p][c]   58.7 MB
__device__ float g_xn[T_ * B_];                // [t][b]
__device__ float g_pn[T_ * P_];                // [t][p]
__device__ float g_sim[(size_t)T_ * B_ * P_];  // [t][b][p]   29.4 MB
__device__ float g_d2[(size_t)T_ * B_ * P_];   // [t][b][p]   29.4 MB

// ---------------- packed f32x2 helpers (Blackwell FFMA2 path) ----------------
// NOTE: f32x2 PTX ops take .b64 regs -> must use "l" constraints, not "d".
typedef unsigned long long u64;

__device__ __forceinline__ u64 pack2(float lo, float hi) {
    u64 d; asm("mov.b64 %0, {%1, %2};" : "=l"(d) : "f"(lo), "f"(hi)); return d;
}
__device__ __forceinline__ float2 unpack2(u64 d) {
    float2 r; asm("mov.b64 {%0, %1}, %2;" : "=f"(r.x), "=f"(r.y) : "l"(d)); return r;
}
__device__ __forceinline__ u64 ffma2(u64 a, u64 b, u64 c) {
    u64 d; asm("fma.rn.f32x2 %0, %1, %2, %3;" : "=l"(d) : "l"(a), "l"(b), "l"(c)); return d;
}

// ---------------- transpose: src [R][C][T] -> dst [T][R][C] ----------------
__global__ void transpose_kernel(const float* __restrict__ src, int which) {
    __shared__ float tile[32][57];
    float* dst = which ? g_pT : g_xT;
    const int R = which ? P_ : B_;
    const int r  = blockIdx.x;
    const int c0 = blockIdx.y * 32;

    const float* s = src + (size_t)r * C_ * T_ + (size_t)c0 * T_;
    for (int idx = threadIdx.x; idx < 32 * T_; idx += blockDim.x)
        tile[idx / T_][idx % T_] = s[idx];
    __syncthreads();
    for (int idx = threadIdx.x; idx < 32 * T_; idx += blockDim.x) {
        int t = idx >> 5, c = idx & 31;
        dst[(size_t)t * R * C_ + (size_t)r * C_ + c0 + c] = tile[c][t];
    }
}

// ---------------- per-(t,row) L2 norm over C (one warp per output) ----------------
__global__ void norm_kernel(int which) {
    const float* src = which ? g_pT : g_xT;
    float* dst = which ? g_pn : g_xn;
    const int R = which ? P_ : B_;
    int gw   = (blockIdx.x * blockDim.x + threadIdx.x) >> 5;
    int lane = threadIdx.x & 31;
    if (gw >= T_ * R) return;
    const float* s = src + (size_t)gw * C_;
    float acc = 0.f;
    #pragma unroll 4
    for (int c = lane; c < C_; c += 32) { float v = s[c]; acc += v * v; }
    #pragma unroll
    for (int o = 16; o > 0; o >>= 1) acc += __shfl_xor_sync(0xffffffffu, acc, o);
    if (lane == 0) dst[gw] = sqrtf(acc);
}

// ---------------- fused dual-accumulator GEMM per t (packed f32x2) ----------------
// Tile: 128 (b) x 64 (p), K-chunk 32, 256 threads.
// Micro-tile: 8 rows x 4 cols x 2 accumulators, packed as 4 row-pairs of f32x2.
#define BT 128
#define PT 64
#define KT 32

__global__ __launch_bounds__(256, 2) void gemm_kernel(const float* __restrict__ fcw) {
    __shared__ float xs [KT][BT + 4];   // row = 132 floats = 528 B (16B-aligned rows)
    __shared__ float xws[KT][BT + 4];
    __shared__ float ps [KT][PT + 4];   // row = 68 floats = 272 B (16B-aligned rows)
    __shared__ float s_fcw[C_];

    const int t  = blockIdx.z;
    const int b0 = blockIdx.y * BT;
    const int p0 = blockIdx.x * PT;
    const int tid = threadIdx.x;
    const int tx = tid & 15;   // p dimension (4 cols each)
    const int ty = tid >> 4;   // b dimension (8 rows each)

    for (int i = tid; i < C_; i += 256) s_fcw[i] = fcw[i];

    // packed accumulators: [row-pair ip][col j], halves = rows (ty*8+2*ip, +1)
    u64 acc1[4][4], acc2[4][4];
    #pragma unroll
    for (int i = 0; i < 4; i++)
        #pragma unroll
        for (int j = 0; j < 4; j++) { acc1[i][j] = 0ull; acc2[i][j] = 0ull; }

    const float* xbase = g_xT + (size_t)t * B_ * C_ + (size_t)b0 * C_;
    const float* pbase = g_pT + (size_t)t * P_ * C_ + (size_t)p0 * C_;

    __syncthreads();  // s_fcw ready

    for (int kc = 0; kc < C_; kc += KT) {
        // stage X tile (128 x 32) + fc_w-scaled copy : 4 float4 per thread
        #pragma unroll
        for (int i = 0; i < 4; i++) {
            int idx = tid + i * 256;
            int r = idx >> 3, q = idx & 7;
            float4 v = *(const float4*)(xbase + (size_t)r * C_ + kc + q * 4);
            int k = q * 4;
            xs[k + 0][r] = v.x;  xs[k + 1][r] = v.y;
            xs[k + 2][r] = v.z;  xs[k + 3][r] = v.w;
            xws[k + 0][r] = v.x * s_fcw[kc + k + 0];
            xws[k + 1][r] = v.y * s_fcw[kc + k + 1];
            xws[k + 2][r] = v.z * s_fcw[kc + k + 2];
            xws[k + 3][r] = v.w * s_fcw[kc + k + 3];
        }
        // stage P tile (64 x 32) : 2 float4 per thread
        #pragma unroll
        for (int i = 0; i < 2; i++) {
            int idx = tid + i * 256;
            int r = idx >> 3, q = idx & 7;
            float4 v = *(const float4*)(pbase + (size_t)r * C_ + kc + q * 4);
            int k = q * 4;
            ps[k + 0][r] = v.x;  ps[k + 1][r] = v.y;
            ps[k + 2][r] = v.z;  ps[k + 3][r] = v.w;
        }
        __syncthreads();

        #pragma unroll
        for (int k = 0; k < KT; k++) {
            // b operands: duplicate each col value into both packed halves
            float4 bv = *(const float4*)&ps[k][tx * 4];
            u64 bb[4] = { pack2(bv.x, bv.x), pack2(bv.y, bv.y),
                          pack2(bv.z, bv.z), pack2(bv.w, bv.w) };
            // a operands: consecutive rows in smem ARE the packed pairs (no pack cost)
            ulonglong2 a01 = *(const ulonglong2*)&xs [k][ty * 8];
            ulonglong2 a23 = *(const ulonglong2*)&xs [k][ty * 8 + 4];
            ulonglong2 w01 = *(const ulonglong2*)&xws[k][ty * 8];
            ulonglong2 w23 = *(const ulonglong2*)&xws[k][ty * 8 + 4];
            u64 ap[4] = { a01.x, a01.y, a23.x, a23.y };
            u64 wp[4] = { w01.x, w01.y, w23.x, w23.y };
            #pragma unroll
            for (int i = 0; i < 4; i++)
                #pragma unroll
                for (int j = 0; j < 4; j++) {
                    acc1[i][j] = ffma2(ap[i], bb[j], acc1[i][j]);
                    acc2[i][j] = ffma2(wp[i], bb[j], acc2[i][j]);
                }
        }
        __syncthreads();
    }

    // epilogue: normalize dots -> sim, write sim + d2 (layout [t][b][p])
    float pnv[4];
    #pragma unroll
    for (int j = 0; j < 4; j++) pnv[j] = g_pn[t * P_ + p0 + tx * 4 + j];

    #pragma unroll
    for (int ip = 0; ip < 4; ip++) {
        float2 u1[4], u2[4];
        #pragma unroll
        for (int j = 0; j < 4; j++) { u1[j] = unpack2(acc1[ip][j]); u2[j] = unpack2(acc2[ip][j]); }
        #pragma unroll
        for (int h = 0; h < 2; h++) {
            int r = b0 + ty * 8 + 2 * ip + h;
            float xnv = g_xn[t * B_ + r];
            size_t off = (size_t)t * B_ * P_ + (size_t)r * P_ + p0 + tx * 4;
            float4 sv, dv;
            float d0 = h ? u1[0].y : u1[0].x, d1 = h ? u1[1].y : u1[1].x;
            float d2v = h ? u1[2].y : u1[2].x, d3 = h ? u1[3].y : u1[3].x;
            sv.x = d0 / fmaxf(xnv * pnv[0], EPSV);
            sv.y = d1 / fmaxf(xnv * pnv[1], EPSV);
            sv.z = d2v / fmaxf(xnv * pnv[2], EPSV);
            sv.w = d3 / fmaxf(xnv * pnv[3], EPSV);
            dv.x = h ? u2[0].y : u2[0].x;  dv.y = h ? u2[1].y : u2[1].x;
            dv.z = h ? u2[2].y : u2[2].x;  dv.w = h ? u2[3].y : u2[3].x;
            *(float4*)(g_sim + off) = sv;
            *(float4*)(g_d2  + off) = dv;
        }
    }
}

// ---------------- online softmax over t + folded FC + relu ----------------
__global__ void softmax_out_kernel(const float* __restrict__ fcb, float* __restrict__ out) {
    const int b = blockIdx.x;
    const int p = threadIdx.x;   // 512 threads
    const float* sp = g_sim + (size_t)b * P_ + p;
    const float* dp = g_d2  + (size_t)b * P_ + p;
    float m = -INFINITY, l = 0.f, acc = 0.f;
    #pragma unroll 4
    for (int t = 0; t < T_; t++) {
        float s = sp[(size_t)t * B_ * P_];
        float v = dp[(size_t)t * B_ * P_];
        float nm = fmaxf(m, s);
        float scale = __expf(m - nm);
        l = l * scale; acc = acc * scale;
        float e = __expf(s - nm);
        l += e; acc += e * v;
        m = nm;
    }
    out[b * P_ + p] = fmaxf(acc / l + fcb[0], 0.f);
}

// ---------------- launch ----------------
extern "C" void kernel_launch(void* const* d_in, const int* in_sizes, int n_in,
                              void* d_out, int out_size) {
    const float* x     = (const float*)d_in[0];
    const float* proto = (const float*)d_in[1];
    const float* fcw   = (const float*)d_in[2];
    const float* fcb   = (const float*)d_in[3];
    float* out = (float*)d_out;
    (void)in_sizes; (void)n_in; (void)out_size;

    transpose_kernel<<<dim3(B_, C_ / 32), 256>>>(x, 0);
    transpose_kernel<<<dim3(P_, C_ / 32), 256>>>(proto, 1);
    norm_kernel<<<(T_ * B_ * 32 + 255) / 256, 256>>>(0);
    norm_kernel<<<(T_ * P_ * 32 + 255) / 256, 256>>>(1);
    gemm_kernel<<<dim3(P_ / PT, B_ / BT, T_), 256>>>(fcw);
    softmax_out_kernel<<<B_, P_>>>(fcb, out);
}

// round 6
// speedup vs baseline: 1.6596x; 1.5280x over previous
#include <cuda_runtime.h>
#include <cuda_bf16.h>
#include <math.h>
#include <cstdint>

#define B_ 256
#define P_ 512
#define C_ 512
#define T_ 56
#define EPSV 1e-8f

// ---------------- static device scratch (allocation-free rule) ----------------
__device__ __nv_bfloat16 g_xh[(size_t)T_ * B_ * C_];   // [t][b][c] hi
__device__ __nv_bfloat16 g_xl[(size_t)T_ * B_ * C_];   // lo
__device__ __nv_bfloat16 g_ph[(size_t)T_ * P_ * C_];   // [t][p][c] hi
__device__ __nv_bfloat16 g_pl[(size_t)T_ * P_ * C_];
__device__ __nv_bfloat16 g_wh[(size_t)T_ * P_ * C_];   // fcw*proto hi
__device__ __nv_bfloat16 g_wl[(size_t)T_ * P_ * C_];
__device__ float g_xpart[(size_t)T_ * B_ * 16];        // partial sumsq
__device__ float g_ppart[(size_t)T_ * P_ * 16];
__device__ float g_xn[T_ * B_];                        // sum of squares
__device__ float g_pn[T_ * P_];
__device__ float g_sim[(size_t)T_ * P_ * B_];          // [t][p][b]
__device__ float g_d2 [(size_t)T_ * P_ * B_];          // [t][p][b]

// ---------------- PTX helpers (plain sm_80+ instructions only) ----------------
__device__ __forceinline__ uint32_t smem_u32(const void* p) {
    uint32_t a;
    asm("{ .reg .u64 t; cvta.to.shared.u64 t, %1; cvt.u32.u64 %0, t; }" : "=r"(a) : "l"(p));
    return a;
}
__device__ __forceinline__ void cp16(uint32_t d, const void* g) {
    asm volatile("cp.async.cg.shared.global [%0], [%1], 16;" :: "r"(d), "l"(g) : "memory");
}
__device__ __forceinline__ void cp_commit() { asm volatile("cp.async.commit_group;" ::: "memory"); }
template<int N> __device__ __forceinline__ void cp_wait() {
    asm volatile("cp.async.wait_group %0;" :: "n"(N) : "memory");
}
__device__ __forceinline__ void ldm_x4(uint32_t* r, uint32_t a) {
    asm volatile("ldmatrix.sync.aligned.m8n8.x4.shared.b16 {%0,%1,%2,%3}, [%4];"
        : "=r"(r[0]), "=r"(r[1]), "=r"(r[2]), "=r"(r[3]) : "r"(a));
}
__device__ __forceinline__ void mma16816(float* d, const uint32_t* a, uint32_t b0, uint32_t b1) {
    asm volatile("mma.sync.aligned.m16n8k16.row.col.f32.bf16.bf16.f32 "
        "{%0,%1,%2,%3}, {%4,%5,%6,%7}, {%8,%9}, {%0,%1,%2,%3};"
        : "+f"(d[0]), "+f"(d[1]), "+f"(d[2]), "+f"(d[3])
        : "r"(a[0]), "r"(a[1]), "r"(a[2]), "r"(a[3]), "r"(b0), "r"(b1));
}

// ---------------- prep: x (B,C,T) -> bf16 hi/lo [t][b][c] + partial sumsq ----------------
__global__ void prep_x_kernel(const float* __restrict__ src) {
    __shared__ float tile[32][57];
    const int r = blockIdx.x, c0 = blockIdx.y * 32;
    const float* s = src + (size_t)r * C_ * T_ + (size_t)c0 * T_;
    for (int idx = threadIdx.x; idx < 32 * T_; idx += blockDim.x)
        tile[idx / T_][idx % T_] = s[idx];
    __syncthreads();
    for (int idx = threadIdx.x; idx < 32 * T_; idx += blockDim.x) {
        int t = idx >> 5, c = idx & 31;
        float v = tile[c][t];
        __nv_bfloat16 h = __float2bfloat16(v);
        __nv_bfloat16 l = __float2bfloat16(v - __bfloat162float(h));
        size_t o = ((size_t)t * B_ + r) * C_ + c0 + c;
        g_xh[o] = h; g_xl[o] = l;
    }
    if (threadIdx.x < T_) {
        int t = threadIdx.x;
        float acc = 0.f;
        #pragma unroll
        for (int c = 0; c < 32; c++) { float v = tile[c][t]; acc += v * v; }
        g_xpart[((size_t)t * B_ + r) * 16 + (c0 >> 5)] = acc;
    }
}

// ---------------- prep: proto (P,C,T) -> p hi/lo + (fcw*p) hi/lo + partial sumsq ----------------
__global__ void prep_p_kernel(const float* __restrict__ src, const float* __restrict__ fcw) {
    __shared__ float tile[32][57];
    __shared__ float wsh[32];
    const int r = blockIdx.x, c0 = blockIdx.y * 32;
    if (threadIdx.x < 32) wsh[threadIdx.x] = fcw[c0 + threadIdx.x];
    const float* s = src + (size_t)r * C_ * T_ + (size_t)c0 * T_;
    for (int idx = threadIdx.x; idx < 32 * T_; idx += blockDim.x)
        tile[idx / T_][idx % T_] = s[idx];
    __syncthreads();
    for (int idx = threadIdx.x; idx < 32 * T_; idx += blockDim.x) {
        int t = idx >> 5, c = idx & 31;
        float v = tile[c][t];
        __nv_bfloat16 h = __float2bfloat16(v);
        __nv_bfloat16 l = __float2bfloat16(v - __bfloat162float(h));
        float wv = v * wsh[c];
        __nv_bfloat16 wh = __float2bfloat16(wv);
        __nv_bfloat16 wl = __float2bfloat16(wv - __bfloat162float(wh));
        size_t o = ((size_t)t * P_ + r) * C_ + c0 + c;
        g_ph[o] = h; g_pl[o] = l; g_wh[o] = wh; g_wl[o] = wl;
    }
    if (threadIdx.x < T_) {
        int t = threadIdx.x;
        float acc = 0.f;
        #pragma unroll
        for (int c = 0; c < 32; c++) { float v = tile[c][t]; acc += v * v; }
        g_ppart[((size_t)t * P_ + r) * 16 + (c0 >> 5)] = acc;
    }
}

// ---------------- reduce partials -> sumsq ----------------
__global__ void reduce_norm_kernel() {
    int i = blockIdx.x * blockDim.x + threadIdx.x;
    if (i < T_ * B_) {
        const float* p = g_xpart + (size_t)i * 16;
        float s = 0.f;
        #pragma unroll
        for (int j = 0; j < 16; j++) s += p[j];
        g_xn[i] = s;
    } else if (i < T_ * B_ + T_ * P_) {
        int j = i - T_ * B_;
        const float* p = g_ppart + (size_t)j * 16;
        float s = 0.f;
        #pragma unroll
        for (int k = 0; k < 16; k++) s += p[k];
        g_pn[j] = s;
    }
}

// ---------------- mma.sync GEMM: CTA 128(b) x 256(n=[p|wp]) per t ----------------
// bf16x3 split: acc += Ah*Bh + Ah*Bl + Al*Bh (fp32 accumulate)
#define KC 32
#define RPB 80                 // bytes per smem row (32 bf16 + 8 pad)
#define TILE_B (128 * RPB)     // 10240 per 128-row tile
#define STAGE_B (6 * TILE_B)   // xh xl ph pl wh wl = 61440
#define GSMEM (2 * STAGE_B)    // 122880

__global__ __launch_bounds__(256, 1) void gemm_mma_kernel() {
    extern __shared__ char sm[];
    const uint32_t sbase = smem_u32(sm);
    const int t = blockIdx.z, b0 = blockIdx.y * 128, p0 = blockIdx.x * 128;
    const int tid = threadIdx.x, wid = tid >> 5, lane = tid & 31;

    const size_t xoff = ((size_t)t * B_ + b0) * C_;
    const size_t poff = ((size_t)t * P_ + p0) * C_;
    const __nv_bfloat16* s0 = g_xh + xoff;
    const __nv_bfloat16* s1 = g_xl + xoff;
    const __nv_bfloat16* s2 = g_ph + poff;
    const __nv_bfloat16* s3 = g_pl + poff;
    const __nv_bfloat16* s4 = g_wh + poff;
    const __nv_bfloat16* s5 = g_wl + poff;

    const int row0 = tid >> 2, seg = tid & 3;   // 64 rows x 4 segs per pass

    auto stage = [&](int ch, int s) {
        uint32_t sb = sbase + (uint32_t)s * STAGE_B + row0 * RPB + seg * 16;
        size_t go  = (size_t)row0 * C_ + ch * KC + seg * 8;
        size_t go1 = go + (size_t)64 * C_;
        const uint32_t R64 = 64 * RPB;
        cp16(sb,                  s0 + go); cp16(sb + R64,              s0 + go1);
        cp16(sb + TILE_B,         s1 + go); cp16(sb + TILE_B + R64,     s1 + go1);
        cp16(sb + 2 * TILE_B,     s2 + go); cp16(sb + 2 * TILE_B + R64, s2 + go1);
        cp16(sb + 3 * TILE_B,     s3 + go); cp16(sb + 3 * TILE_B + R64, s3 + go1);
        cp16(sb + 4 * TILE_B,     s4 + go); cp16(sb + 4 * TILE_B + R64, s4 + go1);
        cp16(sb + 5 * TILE_B,     s5 + go); cp16(sb + 5 * TILE_B + R64, s5 + go1);
    };

    // warp tiling: 2 (m) x 4 (n) warps, 64x64 per warp
    const int rowgrp = wid >> 2, colgrp = wid & 3;
    const int m0 = rowgrp * 64;
    const uint32_t a_off = (uint32_t)m0 * RPB;                       // into xh tile
    const uint32_t b_off = (colgrp < 2 ? 2u * TILE_B : 4u * TILE_B)  // ph or wh tile
                         + (uint32_t)(colgrp & 1) * 64 * RPB;

    // ldmatrix lane address components
    const int grp = lane >> 3, win = lane & 7;
    const uint32_t a_lane = (uint32_t)(((grp & 1) * 8 + win) * RPB + (grp >> 1) * 16);
    const uint32_t b_lane = (uint32_t)(((grp >> 1) * 8 + win) * RPB + (grp & 1) * 16);

    float acc[4][8][4];
    #pragma unroll
    for (int i = 0; i < 4; i++)
        #pragma unroll
        for (int j = 0; j < 8; j++)
            #pragma unroll
            for (int k = 0; k < 4; k++) acc[i][j][k] = 0.f;

    stage(0, 0); cp_commit();

    for (int ch = 0; ch < 16; ch++) {
        if (ch < 15) { stage(ch + 1, (ch + 1) & 1); cp_commit(); cp_wait<1>(); }
        else         { cp_wait<0>(); }
        __syncthreads();
        const uint32_t st = sbase + (uint32_t)(ch & 1) * STAGE_B;
        const uint32_t Ah = st + a_off + a_lane;
        const uint32_t Bh = st + b_off + b_lane;

        #pragma unroll
        for (int ks = 0; ks < 2; ks++) {
            const uint32_t kso = ks * 32;
            uint32_t af[4][4], bf[4][4];
            // combo 1: Ah x Bh
            #pragma unroll
            for (int mt = 0; mt < 4; mt++) ldm_x4(af[mt], Ah + mt * 16 * RPB + kso);
            #pragma unroll
            for (int nt = 0; nt < 4; nt++) ldm_x4(bf[nt], Bh + nt * 16 * RPB + kso);
            #pragma unroll
            for (int mt = 0; mt < 4; mt++)
                #pragma unroll
                for (int nt = 0; nt < 4; nt++) {
                    mma16816(acc[mt][nt * 2],     af[mt], bf[nt][0], bf[nt][1]);
                    mma16816(acc[mt][nt * 2 + 1], af[mt], bf[nt][2], bf[nt][3]);
                }
            // combo 2: Ah x Bl (keep af)
            #pragma unroll
            for (int nt = 0; nt < 4; nt++) ldm_x4(bf[nt], Bh + TILE_B + nt * 16 * RPB + kso);
            #pragma unroll
            for (int mt = 0; mt < 4; mt++)
                #pragma unroll
                for (int nt = 0; nt < 4; nt++) {
                    mma16816(acc[mt][nt * 2],     af[mt], bf[nt][0], bf[nt][1]);
                    mma16816(acc[mt][nt * 2 + 1], af[mt], bf[nt][2], bf[nt][3]);
                }
            // combo 3: Al x Bh
            #pragma unroll
            for (int mt = 0; mt < 4; mt++) ldm_x4(af[mt], Ah + TILE_B + mt * 16 * RPB + kso);
            #pragma unroll
            for (int nt = 0; nt < 4; nt++) ldm_x4(bf[nt], Bh + nt * 16 * RPB + kso);
            #pragma unroll
            for (int mt = 0; mt < 4; mt++)
                #pragma unroll
                for (int nt = 0; nt < 4; nt++) {
                    mma16816(acc[mt][nt * 2],     af[mt], bf[nt][0], bf[nt][1]);
                    mma16816(acc[mt][nt * 2 + 1], af[mt], bf[nt][2], bf[nt][3]);
                }
        }
        __syncthreads();
    }

    // epilogue: stage norms (sumsq), normalize dots, write [t][p][b]
    float* nsm = (float*)sm;
    if (tid < 128)      nsm[tid]       = g_xn[t * B_ + b0 + tid];
    else                nsm[tid]       = g_pn[t * P_ + p0 + tid - 128];
    __syncthreads();

    const int fr = lane >> 2, fc = (lane & 3) * 2;
    const bool is_sim = (colgrp < 2);
    const int plb = (colgrp & 1) * 64;
    float* dst = is_sim ? g_sim : g_d2;
    #pragma unroll
    for (int mt = 0; mt < 4; mt++) {
        const int br0 = m0 + mt * 16 + fr;
        const float sx0 = nsm[br0], sx1 = nsm[br0 + 8];
        #pragma unroll
        for (int n8 = 0; n8 < 8; n8++) {
            const int pidx = plb + n8 * 8 + fc;
            size_t c0a = ((size_t)t * P_ + p0 + pidx) * B_ + b0;
            size_t c1a = c0a + B_;
            float v0 = acc[mt][n8][0], v1 = acc[mt][n8][1];
            float v2 = acc[mt][n8][2], v3 = acc[mt][n8][3];
            if (is_sim) {
                float sp0 = nsm[128 + pidx], sp1 = nsm[128 + pidx + 1];
                v0 /= fmaxf(sqrtf(sx0 * sp0), EPSV);
                v1 /= fmaxf(sqrtf(sx0 * sp1), EPSV);
                v2 /= fmaxf(sqrtf(sx1 * sp0), EPSV);
                v3 /= fmaxf(sqrtf(sx1 * sp1), EPSV);
            }
            dst[c0a + br0]     = v0;
            dst[c1a + br0]     = v1;
            dst[c0a + br0 + 8] = v2;
            dst[c1a + br0 + 8] = v3;
        }
    }
}

// ---------------- softmax over t + folded FC + relu ([t][p][b] layout) ----------------
__global__ void softmax_out_kernel(const float* __restrict__ fcb, float* __restrict__ out) {
    const int p = blockIdx.x;     // 512 blocks
    const int b = threadIdx.x;    // 256 threads
    const float* sp = g_sim + (size_t)p * B_ + b;
    const float* dp = g_d2  + (size_t)p * B_ + b;
    const size_t stride = (size_t)P_ * B_;
    float m = -INFINITY, l = 0.f, acc = 0.f;
    #pragma unroll 4
    for (int t = 0; t < T_; t++) {
        float s = sp[t * stride];
        float v = dp[t * stride];
        float nm = fmaxf(m, s);
        float scale = __expf(m - nm);
        l = l * scale; acc = acc * scale;
        float e = __expf(s - nm);
        l += e; acc += e * v;
        m = nm;
    }
    out[b * P_ + p] = fmaxf(acc / l + fcb[0], 0.f);
}

// ---------------- launch ----------------
extern "C" void kernel_launch(void* const* d_in, const int* in_sizes, int n_in,
                              void* d_out, int out_size) {
    const float* x     = (const float*)d_in[0];
    const float* proto = (const float*)d_in[1];
    const float* fcw   = (const float*)d_in[2];
    const float* fcb   = (const float*)d_in[3];
    float* out = (float*)d_out;
    (void)in_sizes; (void)n_in; (void)out_size;

    cudaFuncSetAttribute(gemm_mma_kernel, cudaFuncAttributeMaxDynamicSharedMemorySize, GSMEM);

    prep_x_kernel<<<dim3(B_, C_ / 32), 256>>>(x);
    prep_p_kernel<<<dim3(P_, C_ / 32), 256>>>(proto, fcw);
    reduce_norm_kernel<<<(T_ * (B_ + P_) + 255) / 256, 256>>>();
    gemm_mma_kernel<<<dim3(P_ / 128, B_ / 128, T_), 256, GSMEM>>>();
    softmax_out_kernel<<<P_, B_>>>(fcb, out);
}

// round 7
// speedup vs baseline: 1.6598x; 1.0001x over previous
#include <cuda_runtime.h>
#include <cuda_bf16.h>
#include <math.h>
#include <cstdint>

#define B_ 256
#define P_ 512
#define C_ 512
#define T_ 56
#define EPSV 1e-8f

// ---------------- static device scratch (allocation-free rule) ----------------
__device__ __nv_bfloat16 g_xh[(size_t)T_ * B_ * C_];   // [t][b][c] hi
__device__ __nv_bfloat16 g_xl[(size_t)T_ * B_ * C_];   // lo
__device__ __nv_bfloat16 g_ph[(size_t)T_ * P_ * C_];   // [t][p][c] hi
__device__ __nv_bfloat16 g_pl[(size_t)T_ * P_ * C_];
__device__ __nv_bfloat16 g_wh[(size_t)T_ * P_ * C_];   // fcw*proto hi
__device__ __nv_bfloat16 g_wl[(size_t)T_ * P_ * C_];
__device__ float g_xpart[(size_t)T_ * B_ * 16];        // partial sumsq
__device__ float g_ppart[(size_t)T_ * P_ * 16];
__device__ float g_xn[T_ * B_];                        // sum of squares
__device__ float g_pn[T_ * P_];
__device__ float g_sim[(size_t)T_ * P_ * B_];          // [t][p][b]
__device__ float g_d2 [(size_t)T_ * P_ * B_];          // [t][p][b]

// ---------------- PTX helpers (plain sm_80+ instructions only) ----------------
__device__ __forceinline__ uint32_t smem_u32(const void* p) {
    uint32_t a;
    asm("{ .reg .u64 t; cvta.to.shared.u64 t, %1; cvt.u32.u64 %0, t; }" : "=r"(a) : "l"(p));
    return a;
}
__device__ __forceinline__ void cp16(uint32_t d, const void* g) {
    asm volatile("cp.async.cg.shared.global [%0], [%1], 16;" :: "r"(d), "l"(g) : "memory");
}
__device__ __forceinline__ void cp_commit() { asm volatile("cp.async.commit_group;" ::: "memory"); }
template<int N> __device__ __forceinline__ void cp_wait() {
    asm volatile("cp.async.wait_group %0;" :: "n"(N) : "memory");
}
__device__ __forceinline__ void ldm_x4(uint32_t* r, uint32_t a) {
    asm volatile("ldmatrix.sync.aligned.m8n8.x4.shared.b16 {%0,%1,%2,%3}, [%4];"
        : "=r"(r[0]), "=r"(r[1]), "=r"(r[2]), "=r"(r[3]) : "r"(a));
}
__device__ __forceinline__ void mma16816(float* d, const uint32_t* a, uint32_t b0, uint32_t b1) {
    asm volatile("mma.sync.aligned.m16n8k16.row.col.f32.bf16.bf16.f32 "
        "{%0,%1,%2,%3}, {%4,%5,%6,%7}, {%8,%9}, {%0,%1,%2,%3};"
        : "+f"(d[0]), "+f"(d[1]), "+f"(d[2]), "+f"(d[3])
        : "r"(a[0]), "r"(a[1]), "r"(a[2]), "r"(a[3]), "r"(b0), "r"(b1));
}

// ---------------- prep: x (B,C,T) -> bf16 hi/lo [t][b][c] + partial sumsq ----------------
__global__ void prep_x_kernel(const float* __restrict__ src) {
    __shared__ float tile[32][57];
    const int r = blockIdx.x, c0 = blockIdx.y * 32;
    const float* s = src + (size_t)r * C_ * T_ + (size_t)c0 * T_;
    for (int idx = threadIdx.x; idx < 32 * T_; idx += blockDim.x)
        tile[idx / T_][idx % T_] = s[idx];
    __syncthreads();
    for (int idx = threadIdx.x; idx < 32 * T_; idx += blockDim.x) {
        int t = idx >> 5, c = idx & 31;
        float v = tile[c][t];
        __nv_bfloat16 h = __float2bfloat16(v);
        __nv_bfloat16 l = __float2bfloat16(v - __bfloat162float(h));
        size_t o = ((size_t)t * B_ + r) * C_ + c0 + c;
        g_xh[o] = h; g_xl[o] = l;
    }
    if (threadIdx.x < T_) {
        int t = threadIdx.x;
        float acc = 0.f;
        #pragma unroll
        for (int c = 0; c < 32; c++) { float v = tile[c][t]; acc += v * v; }
        g_xpart[((size_t)t * B_ + r) * 16 + (c0 >> 5)] = acc;
    }
}

// ---------------- prep: proto (P,C,T) -> p hi/lo + (fcw*p) hi/lo + partial sumsq ----------------
__global__ void prep_p_kernel(const float* __restrict__ src, const float* __restrict__ fcw) {
    __shared__ float tile[32][57];
    __shared__ float wsh[32];
    const int r = blockIdx.x, c0 = blockIdx.y * 32;
    if (threadIdx.x < 32) wsh[threadIdx.x] = fcw[c0 + threadIdx.x];
    const float* s = src + (size_t)r * C_ * T_ + (size_t)c0 * T_;
    for (int idx = threadIdx.x; idx < 32 * T_; idx += blockDim.x)
        tile[idx / T_][idx % T_] = s[idx];
    __syncthreads();
    for (int idx = threadIdx.x; idx < 32 * T_; idx += blockDim.x) {
        int t = idx >> 5, c = idx & 31;
        float v = tile[c][t];
        __nv_bfloat16 h = __float2bfloat16(v);
        __nv_bfloat16 l = __float2bfloat16(v - __bfloat162float(h));
        float wv = v * wsh[c];
        __nv_bfloat16 wh = __float2bfloat16(wv);
        __nv_bfloat16 wl = __float2bfloat16(wv - __bfloat162float(wh));
        size_t o = ((size_t)t * P_ + r) * C_ + c0 + c;
        g_ph[o] = h; g_pl[o] = l; g_wh[o] = wh; g_wl[o] = wl;
    }
    if (threadIdx.x < T_) {
        int t = threadIdx.x;
        float acc = 0.f;
        #pragma unroll
        for (int c = 0; c < 32; c++) { float v = tile[c][t]; acc += v * v; }
        g_ppart[((size_t)t * P_ + r) * 16 + (c0 >> 5)] = acc;
    }
}

// ---------------- reduce partials -> sumsq ----------------
__global__ void reduce_norm_kernel() {
    int i = blockIdx.x * blockDim.x + threadIdx.x;
    if (i < T_ * B_) {
        const float* p = g_xpart + (size_t)i * 16;
        float s = 0.f;
        #pragma unroll
        for (int j = 0; j < 16; j++) s += p[j];
        g_xn[i] = s;
    } else if (i < T_ * B_ + T_ * P_) {
        int j = i - T_ * B_;
        const float* p = g_ppart + (size_t)j * 16;
        float s = 0.f;
        #pragma unroll
        for (int k = 0; k < 16; k++) s += p[k];
        g_pn[j] = s;
    }
}

// ---------------- mma.sync GEMM: CTA 128(b) x 256(n=[p|wp]) per t ----------------
// bf16x3 split: acc += Ah*Bh + Ah*Bl + Al*Bh (fp32 accumulate)
#define KC 32
#define RPB 80                 // bytes per smem row (32 bf16 + 8 pad)
#define TILE_B (128 * RPB)     // 10240 per 128-row tile
#define STAGE_B (6 * TILE_B)   // xh xl ph pl wh wl = 61440
#define GSMEM (2 * STAGE_B)    // 122880

__global__ __launch_bounds__(256, 1) void gemm_mma_kernel() {
    extern __shared__ char sm[];
    const uint32_t sbase = smem_u32(sm);
    const int t = blockIdx.z, b0 = blockIdx.y * 128, p0 = blockIdx.x * 128;
    const int tid = threadIdx.x, wid = tid >> 5, lane = tid & 31;

    const size_t xoff = ((size_t)t * B_ + b0) * C_;
    const size_t poff = ((size_t)t * P_ + p0) * C_;
    const __nv_bfloat16* s0 = g_xh + xoff;
    const __nv_bfloat16* s1 = g_xl + xoff;
    const __nv_bfloat16* s2 = g_ph + poff;
    const __nv_bfloat16* s3 = g_pl + poff;
    const __nv_bfloat16* s4 = g_wh + poff;
    const __nv_bfloat16* s5 = g_wl + poff;

    const int row0 = tid >> 2, seg = tid & 3;   // 64 rows x 4 segs per pass

    auto stage = [&](int ch, int s) {
        uint32_t sb = sbase + (uint32_t)s * STAGE_B + row0 * RPB + seg * 16;
        size_t go  = (size_t)row0 * C_ + ch * KC + seg * 8;
        size_t go1 = go + (size_t)64 * C_;
        const uint32_t R64 = 64 * RPB;
        cp16(sb,                  s0 + go); cp16(sb + R64,              s0 + go1);
        cp16(sb + TILE_B,         s1 + go); cp16(sb + TILE_B + R64,     s1 + go1);
        cp16(sb + 2 * TILE_B,     s2 + go); cp16(sb + 2 * TILE_B + R64, s2 + go1);
        cp16(sb + 3 * TILE_B,     s3 + go); cp16(sb + 3 * TILE_B + R64, s3 + go1);
        cp16(sb + 4 * TILE_B,     s4 + go); cp16(sb + 4 * TILE_B + R64, s4 + go1);
        cp16(sb + 5 * TILE_B,     s5 + go); cp16(sb + 5 * TILE_B + R64, s5 + go1);
    };

    // warp tiling: 2 (m) x 4 (n) warps, 64x64 per warp
    const int rowgrp = wid >> 2, colgrp = wid & 3;
    const int m0 = rowgrp * 64;
    const uint32_t a_off = (uint32_t)m0 * RPB;                       // into xh tile
    const uint32_t b_off = (colgrp < 2 ? 2u * TILE_B : 4u * TILE_B)  // ph or wh tile
                         + (uint32_t)(colgrp & 1) * 64 * RPB;

    // ldmatrix lane address components
    const int grp = lane >> 3, win = lane & 7;
    const uint32_t a_lane = (uint32_t)(((grp & 1) * 8 + win) * RPB + (grp >> 1) * 16);
    const uint32_t b_lane = (uint32_t)(((grp >> 1) * 8 + win) * RPB + (grp & 1) * 16);

    float acc[4][8][4];
    #pragma unroll
    for (int i = 0; i < 4; i++)
        #pragma unroll
        for (int j = 0; j < 8; j++)
            #pragma unroll
            for (int k = 0; k < 4; k++) acc[i][j][k] = 0.f;

    stage(0, 0); cp_commit();

    for (int ch = 0; ch < 16; ch++) {
        if (ch < 15) { stage(ch + 1, (ch + 1) & 1); cp_commit(); cp_wait<1>(); }
        else         { cp_wait<0>(); }
        __syncthreads();
        const uint32_t st = sbase + (uint32_t)(ch & 1) * STAGE_B;
        const uint32_t Ah = st + a_off + a_lane;
        const uint32_t Bh = st + b_off + b_lane;

        #pragma unroll
        for (int ks = 0; ks < 2; ks++) {
            const uint32_t kso = ks * 32;
            uint32_t af[4][4], bf[4][4];
            // combo 1: Ah x Bh
            #pragma unroll
            for (int mt = 0; mt < 4; mt++) ldm_x4(af[mt], Ah + mt * 16 * RPB + kso);
            #pragma unroll
            for (int nt = 0; nt < 4; nt++) ldm_x4(bf[nt], Bh + nt * 16 * RPB + kso);
            #pragma unroll
            for (int mt = 0; mt < 4; mt++)
                #pragma unroll
                for (int nt = 0; nt < 4; nt++) {
                    mma16816(acc[mt][nt * 2],     af[mt], bf[nt][0], bf[nt][1]);
                    mma16816(acc[mt][nt * 2 + 1], af[mt], bf[nt][2], bf[nt][3]);
                }
            // combo 2: Ah x Bl (keep af)
            #pragma unroll
            for (int nt = 0; nt < 4; nt++) ldm_x4(bf[nt], Bh + TILE_B + nt * 16 * RPB + kso);
            #pragma unroll
            for (int mt = 0; mt < 4; mt++)
                #pragma unroll
                for (int nt = 0; nt < 4; nt++) {
                    mma16816(acc[mt][nt * 2],     af[mt], bf[nt][0], bf[nt][1]);
                    mma16816(acc[mt][nt * 2 + 1], af[mt], bf[nt][2], bf[nt][3]);
                }
            // combo 3: Al x Bh
            #pragma unroll
            for (int mt = 0; mt < 4; mt++) ldm_x4(af[mt], Ah + TILE_B + mt * 16 * RPB + kso);
            #pragma unroll
            for (int nt = 0; nt < 4; nt++) ldm_x4(bf[nt], Bh + nt * 16 * RPB + kso);
            #pragma unroll
            for (int mt = 0; mt < 4; mt++)
                #pragma unroll
                for (int nt = 0; nt < 4; nt++) {
                    mma16816(acc[mt][nt * 2],     af[mt], bf[nt][0], bf[nt][1]);
                    mma16816(acc[mt][nt * 2 + 1], af[mt], bf[nt][2], bf[nt][3]);
                }
        }
        __syncthreads();
    }

    // epilogue: stage norms (sumsq), normalize dots, write [t][p][b]
    float* nsm = (float*)sm;
    if (tid < 128)      nsm[tid]       = g_xn[t * B_ + b0 + tid];
    else                nsm[tid]       = g_pn[t * P_ + p0 + tid - 128];
    __syncthreads();

    const int fr = lane >> 2, fc = (lane & 3) * 2;
    const bool is_sim = (colgrp < 2);
    const int plb = (colgrp & 1) * 64;
    float* dst = is_sim ? g_sim : g_d2;
    #pragma unroll
    for (int mt = 0; mt < 4; mt++) {
        const int br0 = m0 + mt * 16 + fr;
        const float sx0 = nsm[br0], sx1 = nsm[br0 + 8];
        #pragma unroll
        for (int n8 = 0; n8 < 8; n8++) {
            const int pidx = plb + n8 * 8 + fc;
            size_t c0a = ((size_t)t * P_ + p0 + pidx) * B_ + b0;
            size_t c1a = c0a + B_;
            float v0 = acc[mt][n8][0], v1 = acc[mt][n8][1];
            float v2 = acc[mt][n8][2], v3 = acc[mt][n8][3];
            if (is_sim) {
                float sp0 = nsm[128 + pidx], sp1 = nsm[128 + pidx + 1];
                v0 /= fmaxf(sqrtf(sx0 * sp0), EPSV);
                v1 /= fmaxf(sqrtf(sx0 * sp1), EPSV);
                v2 /= fmaxf(sqrtf(sx1 * sp0), EPSV);
                v3 /= fmaxf(sqrtf(sx1 * sp1), EPSV);
            }
            dst[c0a + br0]     = v0;
            dst[c1a + br0]     = v1;
            dst[c0a + br0 + 8] = v2;
            dst[c1a + br0 + 8] = v3;
        }
    }
}

// ---------------- softmax over t + folded FC + relu ([t][p][b] layout) ----------------
__global__ void softmax_out_kernel(const float* __restrict__ fcb, float* __restrict__ out) {
    const int p = blockIdx.x;     // 512 blocks
    const int b = threadIdx.x;    // 256 threads
    const float* sp = g_sim + (size_t)p * B_ + b;
    const float* dp = g_d2  + (size_t)p * B_ + b;
    const size_t stride = (size_t)P_ * B_;
    float m = -INFINITY, l = 0.f, acc = 0.f;
    #pragma unroll 4
    for (int t = 0; t < T_; t++) {
        float s = sp[t * stride];
        float v = dp[t * stride];
        float nm = fmaxf(m, s);
        float scale = __expf(m - nm);
        l = l * scale; acc = acc * scale;
        float e = __expf(s - nm);
        l += e; acc += e * v;
        m = nm;
    }
    out[b * P_ + p] = fmaxf(acc / l + fcb[0], 0.f);
}

// ---------------- launch ----------------
extern "C" void kernel_launch(void* const* d_in, const int* in_sizes, int n_in,
                              void* d_out, int out_size) {
    const float* x     = (const float*)d_in[0];
    const float* proto = (const float*)d_in[1];
    const float* fcw   = (const float*)d_in[2];
    const float* fcb   = (const float*)d_in[3];
    float* out = (float*)d_out;
    (void)in_sizes; (void)n_in; (void)out_size;

    cudaFuncSetAttribute(gemm_mma_kernel, cudaFuncAttributeMaxDynamicSharedMemorySize, GSMEM);

    prep_x_kernel<<<dim3(B_, C_ / 32), 256>>>(x);
    prep_p_kernel<<<dim3(P_, C_ / 32), 256>>>(proto, fcw);
    reduce_norm_kernel<<<(T_ * (B_ + P_) + 255) / 256, 256>>>();
    gemm_mma_kernel<<<dim3(P_ / 128, B_ / 128, T_), 256, GSMEM>>>();
    softmax_out_kernel<<<P_, B_>>>(fcb, out);
}